// round 12
// baseline (speedup 1.0000x reference)
#include <cuda_runtime.h>
#include <stdint.h>

#define NB 32768
#define NE 1024
#define NT 128          // threads per CTA
#define EPT 8           // elements per thread (NT*EPT == NE)

// add on the FMA pipe: d = a*one + b (one==1, opaque runtime value -> IMAD)
static __device__ __forceinline__ uint32_t fadd(uint32_t a, uint32_t b, uint32_t one) {
    uint32_t d;
    asm("mad.lo.u32 %0, %1, %2, %3;" : "=r"(d) : "r"(a), "r"(one), "r"(b));
    return d;
}
#define FADDC(d, a, C) asm("mad.lo.u32 %0, %1, %2, %3;" : "=r"(d) : "r"(a), "r"(one), "n"(C))

static __device__ __forceinline__ uint32_t rotl32(uint32_t x, int r) {
    return __funnelshift_l(x, x, r);
}

static __device__ __forceinline__ void prefetch_l2(const void* p) {
    asm volatile("prefetch.global.L2 [%0];" :: "l"(p));
}

// threefry2x32, key (0,42), block (0,i). Returns x0^x1 after 20 rounds —
// matches jax _threefry_random_bits_partitionable (bit_width=32).
// Caller pre-adds ks1=42 into x1. Adds forced to IMAD (fma pipe);
// rotates stay SHF+LOP3 (alu pipe) — empirically the fastest form.
static __device__ __forceinline__ uint32_t tf(uint32_t x1, uint32_t one) {
    uint32_t x0;
    x0 = x1;                 x1 = rotl32(x1, 13) ^ x0;
    x0 = fadd(x0, x1, one);  x1 = rotl32(x1, 15) ^ x0;
    x0 = fadd(x0, x1, one);  x1 = rotl32(x1, 26) ^ x0;
    x0 = fadd(x0, x1, one);  x1 = rotl32(x1,  6) ^ x0;
    FADDC(x0, x0, 42u);  FADDC(x1, x1, 0x1BD11BF0u + 1u);
    x0 = fadd(x0, x1, one);  x1 = rotl32(x1, 17) ^ x0;
    x0 = fadd(x0, x1, one);  x1 = rotl32(x1, 29) ^ x0;
    x0 = fadd(x0, x1, one);  x1 = rotl32(x1, 16) ^ x0;
    x0 = fadd(x0, x1, one);  x1 = rotl32(x1, 24) ^ x0;
    FADDC(x0, x0, 0x1BD11BF0u);  FADDC(x1, x1, 2u);
    x0 = fadd(x0, x1, one);  x1 = rotl32(x1, 13) ^ x0;
    x0 = fadd(x0, x1, one);  x1 = rotl32(x1, 15) ^ x0;
    x0 = fadd(x0, x1, one);  x1 = rotl32(x1, 26) ^ x0;
    x0 = fadd(x0, x1, one);  x1 = rotl32(x1,  6) ^ x0;
    /* x0 += ks0 (=0) */     FADDC(x1, x1, 45u);
    x0 = fadd(x0, x1, one);  x1 = rotl32(x1, 17) ^ x0;
    x0 = fadd(x0, x1, one);  x1 = rotl32(x1, 29) ^ x0;
    x0 = fadd(x0, x1, one);  x1 = rotl32(x1, 16) ^ x0;
    x0 = fadd(x0, x1, one);  x1 = rotl32(x1, 24) ^ x0;
    FADDC(x0, x0, 42u);  FADDC(x1, x1, 0x1BD11BF0u + 4u);
    x0 = fadd(x0, x1, one);  x1 = rotl32(x1, 13) ^ x0;
    x0 = fadd(x0, x1, one);  x1 = rotl32(x1, 15) ^ x0;
    x0 = fadd(x0, x1, one);  x1 = rotl32(x1, 26) ^ x0;
    x0 = fadd(x0, x1, one);  x1 = rotl32(x1,  6) ^ x0;
    FADDC(x0, x0, 0x1BD11BF0u);  FADDC(x1, x1, 5u);
    return x0 ^ x1;
}

__global__ __launch_bounds__(NT)
void dnm_kernel(const float4* __restrict__ embeds,
                const float* __restrict__ factors,
                const float4* __restrict__ mask_token,
                float4* __restrict__ out_embeds,
                float4* __restrict__ out_mask,
                uint32_t one) {
    __shared__ uint32_t sh_hist[256];
    __shared__ unsigned long long sh_cand[1040];   // unique keys (m<<10)|col
    __shared__ int sh_cnt;
    __shared__ int sh_k;
    __shared__ int sh_bucket;
    __shared__ int sh_rem;
    __shared__ uint32_t sh_thrM;
    __shared__ uint32_t sh_thrC;
    __shared__ uint32_t sh_thrFast;  // (thrM<<9)|511 if thrM unique, else 0

    const int row = blockIdx.x;
    const int tid = threadIdx.x;
    const uint32_t M8 = one << 8;    // opaque: umulhi(x,M8) == x>>24 (fma pipe)

    // Warm L2 early without holding destination registers across tf.
    const float4* e_ptr  = embeds + (size_t)row * (NE / 4) + tid * 2;
    const float4* mt_ptr = mask_token + tid * 2;
    prefetch_l2(e_ptr);
    prefetch_l2(mt_ptr);

    sh_hist[tid] = 0u;
    sh_hist[tid + NT] = 0u;
    if (tid == 0) {
        sh_cnt = 0;
        const float f = __ldg(&factors[row]);
        int k = (int)floorf(307.2f * f);   // f32(1024*0.3)*factor, floor
        sh_k = k < 1 ? 1 : k;
    }
    __syncthreads();

    // ---- Phase 1: RNG for 8 contiguous columns + fused histogram ---------
    // Rank order = (bits>>9) asc, ties by column asc (stable argsort).
    uint32_t bits[EPT];
    const uint32_t base = (uint32_t)(row * NE + tid * EPT) + 42u;  // +ks1 baked in
    #pragma unroll
    for (int j = 0; j < EPT; j++) {
        bits[j] = tf(base + j, one);
        atomicAdd(&sh_hist[__umulhi(bits[j], M8)], 1u);   // bucket = bits>>24
    }

    // Real loads now (L2-resident); latency hides behind phases 2-4.
    const float4 e0  = e_ptr[0];
    const float4 e1  = e_ptr[1];
    const float4 mt0 = __ldg(mt_ptr);
    const float4 mt1 = __ldg(mt_ptr + 1);
    __syncthreads();

    // ---- Phase 2: warp 0 scans 256 bins for the k-th-smallest bucket -----
    if (tid < 32) {
        const int lane = tid;
        uint32_t v[8];
        uint32_t s = 0;
        #pragma unroll
        for (int t = 0; t < 8; t++) { v[t] = sh_hist[lane * 8 + t]; s += v[t]; }
        uint32_t incl = s;
        #pragma unroll
        for (int o = 1; o < 32; o <<= 1) {
            uint32_t n = __shfl_up_sync(0xFFFFFFFFu, incl, o);
            if (lane >= o) incl += n;
        }
        const uint32_t excl = incl - s;
        const uint32_t k = (uint32_t)sh_k;
        if (excl < k && k <= incl) {            // unique lane
            uint32_t c = excl;
            #pragma unroll
            for (int t = 0; t < 8; t++) {
                if (k <= c + v[t]) { sh_bucket = lane * 8 + t; sh_rem = (int)(k - c); break; }
                c += v[t];
            }
        }
    }
    __syncthreads();

    // ---- Phase 3: collect boundary-bucket candidates as unique keys ------
    const uint32_t bkt = (uint32_t)sh_bucket;
    #pragma unroll
    for (int j = 0; j < EPT; j++) {
        if (__umulhi(bits[j], M8) == bkt) {               // bits>>24 on fma pipe
            const int p = atomicAdd(&sh_cnt, 1);
            sh_cand[p] = ((unsigned long long)(bits[j] >> 9) << 10)
                         | (unsigned)(tid * EPT + j);
        }
    }
    __syncthreads();

    // ---- Phase 4: warp 0 ranks candidates; uniq folded into same loop ----
    if (tid < 32) {
        const int c = sh_cnt;
        const int rem = sh_rem;
        for (int idx = tid; idx < c; idx += 32) {
            const unsigned long long key = sh_cand[idx];
            const uint32_t mi = (uint32_t)(key >> 10);
            int rank = 0, eq = 0;
            for (int j2 = 0; j2 < c; j2++) {
                const unsigned long long kj = sh_cand[j2];
                rank += (kj < key);
                eq   += ((uint32_t)(kj >> 10) == mi);   // counts self
            }
            if (rank == rem - 1) {                       // unique winner lane
                sh_thrM = mi;
                sh_thrC = (uint32_t)key & 1023u;
                sh_thrFast = (eq == 1) ? ((mi << 9) | 511u) : 0u;
            }
        }
    }
    __syncthreads();

    // ---- Phase 5: apply mask -------------------------------------------
    bool kk[EPT];
    const uint32_t tF = sh_thrFast;
    if (tF) {
        // thrM unique in row: masked <=> bits <= (thrM<<9)|511
        #pragma unroll
        for (int j = 0; j < EPT; j++) kk[j] = bits[j] <= tF;
    } else {
        // rare (~5 rows / 32768): exact lexicographic tie-break by column
        const uint32_t thrM = sh_thrM;
        const uint32_t thrC = sh_thrC;
        const uint32_t cbase = (uint32_t)(tid * EPT);
        #pragma unroll
        for (int j = 0; j < EPT; j++) {
            const uint32_t mj = bits[j] >> 9;
            kk[j] = (mj < thrM) || ((mj == thrM) && (cbase + j <= thrC));
        }
    }

    float4 oe0, oe1, om0, om1;
    oe0.x = kk[0] ? mt0.x : e0.x;  om0.x = kk[0] ? 0.0f : 1.0f;
    oe0.y = kk[1] ? mt0.y : e0.y;  om0.y = kk[1] ? 0.0f : 1.0f;
    oe0.z = kk[2] ? mt0.z : e0.z;  om0.z = kk[2] ? 0.0f : 1.0f;
    oe0.w = kk[3] ? mt0.w : e0.w;  om0.w = kk[3] ? 0.0f : 1.0f;
    oe1.x = kk[4] ? mt1.x : e1.x;  om1.x = kk[4] ? 0.0f : 1.0f;
    oe1.y = kk[5] ? mt1.y : e1.y;  om1.y = kk[5] ? 0.0f : 1.0f;
    oe1.z = kk[6] ? mt1.z : e1.z;  om1.z = kk[6] ? 0.0f : 1.0f;
    oe1.w = kk[7] ? mt1.w : e1.w;  om1.w = kk[7] ? 0.0f : 1.0f;

    float4* oe_ptr = out_embeds + (size_t)row * (NE / 4) + tid * 2;
    float4* om_ptr = out_mask   + (size_t)row * (NE / 4) + tid * 2;
    oe_ptr[0] = oe0;
    oe_ptr[1] = oe1;
    om_ptr[0] = om0;
    om_ptr[1] = om1;
}

extern "C" void kernel_launch(void* const* d_in, const int* in_sizes, int n_in,
                              void* d_out, int out_size) {
    const float4* embeds = (const float4*)d_in[0];     // [32768, 1024] f32
    const float* factors = (const float*)d_in[1];      // [32768] f32
    const float4* mask_token = (const float4*)d_in[2]; // [1, 1024] f32

    float* out = (float*)d_out;
    float4* out_embeds = (float4*)out;                       // [B, E]
    float4* out_mask = (float4*)(out + (size_t)NB * NE);     // [B, E]

    dnm_kernel<<<NB, NT>>>(embeds, factors, mask_token, out_embeds, out_mask, 1u);
}

// round 13
// speedup vs baseline: 1.0014x; 1.0014x over previous
#include <cuda_runtime.h>
#include <stdint.h>

#define NB 32768
#define NE 1024
#define NT 256

// add on the FMA pipe: d = a*one + b (one==1, opaque runtime value -> IMAD)
static __device__ __forceinline__ uint32_t fadd(uint32_t a, uint32_t b, uint32_t one) {
    uint32_t d;
    asm("mad.lo.u32 %0, %1, %2, %3;" : "=r"(d) : "r"(a), "r"(one), "r"(b));
    return d;
}
#define FADDC(d, a, C) asm("mad.lo.u32 %0, %1, %2, %3;" : "=r"(d) : "r"(a), "r"(one), "n"(C))

static __device__ __forceinline__ uint32_t rotl32(uint32_t x, int r) {
    return __funnelshift_l(x, x, r);
}

// threefry2x32, key (0,42), block (0,i). Returns x0^x1 after 20 rounds —
// matches jax _threefry_random_bits_partitionable (bit_width=32).
// Caller pre-adds ks1=42 into x1. Adds forced to IMAD (fma pipe);
// rotates stay SHF+LOP3 (alu pipe) — empirically the fastest form.
static __device__ __forceinline__ uint32_t tf(uint32_t x1, uint32_t one) {
    uint32_t x0;
    x0 = x1;                 x1 = rotl32(x1, 13) ^ x0;
    x0 = fadd(x0, x1, one);  x1 = rotl32(x1, 15) ^ x0;
    x0 = fadd(x0, x1, one);  x1 = rotl32(x1, 26) ^ x0;
    x0 = fadd(x0, x1, one);  x1 = rotl32(x1,  6) ^ x0;
    FADDC(x0, x0, 42u);  FADDC(x1, x1, 0x1BD11BF0u + 1u);
    x0 = fadd(x0, x1, one);  x1 = rotl32(x1, 17) ^ x0;
    x0 = fadd(x0, x1, one);  x1 = rotl32(x1, 29) ^ x0;
    x0 = fadd(x0, x1, one);  x1 = rotl32(x1, 16) ^ x0;
    x0 = fadd(x0, x1, one);  x1 = rotl32(x1, 24) ^ x0;
    FADDC(x0, x0, 0x1BD11BF0u);  FADDC(x1, x1, 2u);
    x0 = fadd(x0, x1, one);  x1 = rotl32(x1, 13) ^ x0;
    x0 = fadd(x0, x1, one);  x1 = rotl32(x1, 15) ^ x0;
    x0 = fadd(x0, x1, one);  x1 = rotl32(x1, 26) ^ x0;
    x0 = fadd(x0, x1, one);  x1 = rotl32(x1,  6) ^ x0;
    /* x0 += ks0 (=0) */     FADDC(x1, x1, 45u);
    x0 = fadd(x0, x1, one);  x1 = rotl32(x1, 17) ^ x0;
    x0 = fadd(x0, x1, one);  x1 = rotl32(x1, 29) ^ x0;
    x0 = fadd(x0, x1, one);  x1 = rotl32(x1, 16) ^ x0;
    x0 = fadd(x0, x1, one);  x1 = rotl32(x1, 24) ^ x0;
    FADDC(x0, x0, 42u);  FADDC(x1, x1, 0x1BD11BF0u + 4u);
    x0 = fadd(x0, x1, one);  x1 = rotl32(x1, 13) ^ x0;
    x0 = fadd(x0, x1, one);  x1 = rotl32(x1, 15) ^ x0;
    x0 = fadd(x0, x1, one);  x1 = rotl32(x1, 26) ^ x0;
    x0 = fadd(x0, x1, one);  x1 = rotl32(x1,  6) ^ x0;
    FADDC(x0, x0, 0x1BD11BF0u);  FADDC(x1, x1, 5u);
    return x0 ^ x1;
}

__global__ __launch_bounds__(NT)
void dnm_kernel(const float4* __restrict__ embeds,
                const float* __restrict__ factors,
                const float4* __restrict__ mask_token,
                float4* __restrict__ out_embeds,
                float4* __restrict__ out_mask,
                uint32_t one) {
    // Two rows per CTA: independent selection state per row.
    __shared__ uint32_t sh_hist[2][256];
    __shared__ unsigned long long sh_cand[2][1040];
    __shared__ int sh_cnt[2];
    __shared__ int sh_k[2];
    __shared__ int sh_bkt[2];
    __shared__ int sh_rem[2];
    __shared__ uint32_t sh_thrM[2];
    __shared__ uint32_t sh_thrC[2];
    __shared__ uint32_t sh_thrF[2];   // (thrM<<9)|511 if unique, else 0

    const int rowA = blockIdx.x * 2;
    const int tid = threadIdx.x;
    const uint32_t M8 = one << 8;     // opaque: umulhi(x,M8) == x>>24 (fma pipe)

    // Early register prefetch (empirically best placement).
    const float4 eA = embeds[(size_t)rowA * (NE / 4) + tid];
    const float4 eB = embeds[(size_t)(rowA + 1) * (NE / 4) + tid];
    const float4 mt = __ldg(&mask_token[tid]);   // shared by both rows

    sh_hist[0][tid] = 0u;
    sh_hist[1][tid] = 0u;
    if (tid < 2) {
        sh_cnt[tid] = 0;
        const float f = __ldg(&factors[rowA + tid]);
        int k = (int)floorf(307.2f * f);   // f32(1024*0.3)*factor, floor
        sh_k[tid] = k < 1 ? 1 : k;
    }
    __syncthreads();                                          // barrier 1

    // ---- Phase 1: RNG for both rows (4 contiguous cols each) + histogram -
    // Rank order = (bits>>9) asc, ties by column asc (stable argsort).
    uint32_t ba[4], bb[4];
    const uint32_t baseA = (uint32_t)(rowA * NE + tid * 4) + 42u;  // +ks1
    #pragma unroll
    for (int j = 0; j < 4; j++) {
        ba[j] = tf(baseA + j, one);
        atomicAdd(&sh_hist[0][__umulhi(ba[j], M8)], 1u);
        bb[j] = tf(baseA + NE + j, one);
        atomicAdd(&sh_hist[1][__umulhi(bb[j], M8)], 1u);
    }
    __syncthreads();                                          // barrier 2

    // ---- Phase 2: warp0 scans row A's bins, warp1 scans row B's ----------
    if (tid < 64) {
        const int r = tid >> 5;                 // 0 = row A, 1 = row B
        const int lane = tid & 31;
        const uint32_t* hist = sh_hist[r];
        uint32_t v[8];
        uint32_t s = 0;
        #pragma unroll
        for (int t = 0; t < 8; t++) { v[t] = hist[lane * 8 + t]; s += v[t]; }
        uint32_t incl = s;
        #pragma unroll
        for (int o = 1; o < 32; o <<= 1) {
            uint32_t n = __shfl_up_sync(0xFFFFFFFFu, incl, o);
            if (lane >= o) incl += n;
        }
        const uint32_t excl = incl - s;
        const uint32_t k = (uint32_t)sh_k[r];
        if (excl < k && k <= incl) {            // unique lane per warp
            uint32_t c = excl;
            #pragma unroll
            for (int t = 0; t < 8; t++) {
                if (k <= c + v[t]) { sh_bkt[r] = lane * 8 + t; sh_rem[r] = (int)(k - c); break; }
                c += v[t];
            }
        }
    }
    __syncthreads();                                          // barrier 3

    // ---- Phase 3: collect boundary-bucket candidates for both rows -------
    const uint32_t bktA = (uint32_t)sh_bkt[0];
    const uint32_t bktB = (uint32_t)sh_bkt[1];
    #pragma unroll
    for (int j = 0; j < 4; j++) {
        if (__umulhi(ba[j], M8) == bktA) {
            const int p = atomicAdd(&sh_cnt[0], 1);
            sh_cand[0][p] = ((unsigned long long)(ba[j] >> 9) << 10)
                            | (unsigned)(tid * 4 + j);
        }
        if (__umulhi(bb[j], M8) == bktB) {
            const int p = atomicAdd(&sh_cnt[1], 1);
            sh_cand[1][p] = ((unsigned long long)(bb[j] >> 9) << 10)
                            | (unsigned)(tid * 4 + j);
        }
    }
    __syncthreads();                                          // barrier 4

    // ---- Phase 4: warp0 ranks row A candidates, warp1 ranks row B --------
    if (tid < 64) {
        const int r = tid >> 5;
        const int lane = tid & 31;
        const int c = sh_cnt[r];
        const int rem = sh_rem[r];
        const unsigned long long* cand = sh_cand[r];
        for (int idx = lane; idx < c; idx += 32) {
            const unsigned long long key = cand[idx];
            const uint32_t mi = (uint32_t)(key >> 10);
            int rank = 0, eq = 0;
            for (int j2 = 0; j2 < c; j2++) {
                const unsigned long long kj = cand[j2];
                rank += (kj < key);
                eq   += ((uint32_t)(kj >> 10) == mi);   // counts self
            }
            if (rank == rem - 1) {                       // unique winner lane
                sh_thrM[r] = mi;
                sh_thrC[r] = (uint32_t)key & 1023u;
                sh_thrF[r] = (eq == 1) ? ((mi << 9) | 511u) : 0u;
            }
        }
    }
    __syncthreads();                                          // barrier 5

    // ---- Phase 5: apply masks for both rows ------------------------------
    const uint32_t cbase = (uint32_t)(tid * 4);
    bool kA[4], kB[4];

    const uint32_t tFA = sh_thrF[0];
    if (tFA) {
        #pragma unroll
        for (int j = 0; j < 4; j++) kA[j] = ba[j] <= tFA;
    } else {    // rare: exact lexicographic tie-break
        const uint32_t thrM = sh_thrM[0], thrC = sh_thrC[0];
        #pragma unroll
        for (int j = 0; j < 4; j++) {
            const uint32_t mj = ba[j] >> 9;
            kA[j] = (mj < thrM) || ((mj == thrM) && (cbase + j <= thrC));
        }
    }
    const uint32_t tFB = sh_thrF[1];
    if (tFB) {
        #pragma unroll
        for (int j = 0; j < 4; j++) kB[j] = bb[j] <= tFB;
    } else {
        const uint32_t thrM = sh_thrM[1], thrC = sh_thrC[1];
        #pragma unroll
        for (int j = 0; j < 4; j++) {
            const uint32_t mj = bb[j] >> 9;
            kB[j] = (mj < thrM) || ((mj == thrM) && (cbase + j <= thrC));
        }
    }

    float4 oeA, omA, oeB, omB;
    oeA.x = kA[0] ? mt.x : eA.x;  omA.x = kA[0] ? 0.0f : 1.0f;
    oeA.y = kA[1] ? mt.y : eA.y;  omA.y = kA[1] ? 0.0f : 1.0f;
    oeA.z = kA[2] ? mt.z : eA.z;  omA.z = kA[2] ? 0.0f : 1.0f;
    oeA.w = kA[3] ? mt.w : eA.w;  omA.w = kA[3] ? 0.0f : 1.0f;
    oeB.x = kB[0] ? mt.x : eB.x;  omB.x = kB[0] ? 0.0f : 1.0f;
    oeB.y = kB[1] ? mt.y : eB.y;  omB.y = kB[1] ? 0.0f : 1.0f;
    oeB.z = kB[2] ? mt.z : eB.z;  omB.z = kB[2] ? 0.0f : 1.0f;
    oeB.w = kB[3] ? mt.w : eB.w;  omB.w = kB[3] ? 0.0f : 1.0f;

    out_embeds[(size_t)rowA * (NE / 4) + tid] = oeA;
    out_embeds[(size_t)(rowA + 1) * (NE / 4) + tid] = oeB;
    out_mask[(size_t)rowA * (NE / 4) + tid] = omA;
    out_mask[(size_t)(rowA + 1) * (NE / 4) + tid] = omB;
}

extern "C" void kernel_launch(void* const* d_in, const int* in_sizes, int n_in,
                              void* d_out, int out_size) {
    const float4* embeds = (const float4*)d_in[0];     // [32768, 1024] f32
    const float* factors = (const float*)d_in[1];      // [32768] f32
    const float4* mask_token = (const float4*)d_in[2]; // [1, 1024] f32

    float* out = (float*)d_out;
    float4* out_embeds = (float4*)out;                       // [B, E]
    float4* out_mask = (float4*)(out + (size_t)NB * NE);     // [B, E]

    dnm_kernel<<<NB / 2, NT>>>(embeds, factors, mask_token, out_embeds, out_mask, 1u);
}